// round 16
// baseline (speedup 1.0000x reference)
#include <cuda_runtime.h>

// MaxPool 2x2 stride 2, (16,64,512,512) fp32 -> (16,64,256,256) fp32.
// FINAL — converged at the GB300 DRAM-interface ceiling.
//   harness: 186.14-186.78us over 5 samples (sigma ~0.24us)
//   ncu:     181.3-182.3us, 7268-7305 GB/s = 91-92% of 8TB/s HBM spec
//
// Why this is the ceiling (all measured): 1.34GB stream-once traffic, zero
// reuse, compute <7% busy. Controlled experiment: LDG.256 halved L1tex work
// (38.7%->22.3%) with ZERO duration change -> DRAM interface alone sets the
// time; the ~8% gap to spec is 4:1 read/write turnaround + refresh.
//
// Config: one thread -> one float4 output via 4x coalesced LDG.128 (__ldcg,
// L2-only for stream-once data) + 1x STG.128; 64-thread CTAs (262,144
// blocks) so the HW rasterizer supplies deep free MLP.
//
// Rejected by measurement: persistent 1-wave grid (204.9us), 64B/thread
// spread loads (188.4us), f2-out / warp-row-pair / MLP8 layouts, __stcs/
// __ldcs hints, 256/128-thr grains, LDG.256 — all within noise or worse.

#define IN_H 512
#define OUT_H 256
#define BC (16 * 64)

#define IN_ROW_F4 128   // 512 floats / 4
#define OUT_ROW_F4 64   // 256 floats / 4

__global__ void maxpool2x2_kernel(const float4* __restrict__ in4,
                                  float4* __restrict__ out4) {
    unsigned tid = blockIdx.x * blockDim.x + threadIdx.x;

    unsigned ox4  = tid & (OUT_ROW_F4 - 1);         // [0, 64)
    unsigned rest = tid >> 6;
    unsigned oy   = rest & (OUT_H - 1);             // [0, 256)
    unsigned bc   = rest >> 8;                      // [0, 1024)

    unsigned ibase = bc * (IN_H * IN_ROW_F4) + (oy * 2) * IN_ROW_F4 + ox4 * 2;

    float4 r0a = __ldcg(&in4[ibase]);
    float4 r0b = __ldcg(&in4[ibase + 1]);
    float4 r1a = __ldcg(&in4[ibase + IN_ROW_F4]);
    float4 r1b = __ldcg(&in4[ibase + IN_ROW_F4 + 1]);

    float4 o;
    o.x = fmaxf(fmaxf(r0a.x, r0a.y), fmaxf(r1a.x, r1a.y));
    o.y = fmaxf(fmaxf(r0a.z, r0a.w), fmaxf(r1a.z, r1a.w));
    o.z = fmaxf(fmaxf(r0b.x, r0b.y), fmaxf(r1b.x, r1b.y));
    o.w = fmaxf(fmaxf(r0b.z, r0b.w), fmaxf(r1b.z, r1b.w));

    out4[tid] = o;
}

extern "C" void kernel_launch(void* const* d_in, const int* in_sizes, int n_in,
                              void* d_out, int out_size) {
    const float4* in4 = (const float4*)d_in[0];
    float4* out4 = (float4*)d_out;

    const unsigned total = (unsigned)BC * OUT_H * OUT_ROW_F4;  // 16,777,216
    const int threads = 64;
    const unsigned blocks = total / threads;                   // 262,144

    maxpool2x2_kernel<<<blocks, threads>>>(in4, out4);
}

// round 17
// speedup vs baseline: 1.0007x; 1.0007x over previous
#include <cuda_runtime.h>

// MaxPool 2x2 stride 2, (16,64,512,512) fp32 -> (16,64,256,256) fp32.
// Converged DRAM-ceiling config (92% of 8TB/s HBM spec) with the LAST
// untried cache-policy point: __stwt (write-through) stores. Hypothesis:
// write-back dirty-line drain interleaves with the read stream at the DRAM
// scheduler (the ~8% turnaround tax); write-through may smooth the write
// stream. Read side byte-identical to the measured winner: one thread ->
// one float4 output via 4x coalesced LDG.128 (__ldcg) + 1x 128-bit store;
// 64-thread CTAs (262,144 blocks).

#define IN_H 512
#define OUT_H 256
#define BC (16 * 64)

#define IN_ROW_F4 128   // 512 floats / 4
#define OUT_ROW_F4 64   // 256 floats / 4

__global__ void maxpool2x2_kernel(const float4* __restrict__ in4,
                                  float4* __restrict__ out4) {
    unsigned tid = blockIdx.x * blockDim.x + threadIdx.x;

    unsigned ox4  = tid & (OUT_ROW_F4 - 1);         // [0, 64)
    unsigned rest = tid >> 6;
    unsigned oy   = rest & (OUT_H - 1);             // [0, 256)
    unsigned bc   = rest >> 8;                      // [0, 1024)

    unsigned ibase = bc * (IN_H * IN_ROW_F4) + (oy * 2) * IN_ROW_F4 + ox4 * 2;

    float4 r0a = __ldcg(&in4[ibase]);
    float4 r0b = __ldcg(&in4[ibase + 1]);
    float4 r1a = __ldcg(&in4[ibase + IN_ROW_F4]);
    float4 r1b = __ldcg(&in4[ibase + IN_ROW_F4 + 1]);

    float4 o;
    o.x = fmaxf(fmaxf(r0a.x, r0a.y), fmaxf(r1a.x, r1a.y));
    o.y = fmaxf(fmaxf(r0a.z, r0a.w), fmaxf(r1a.z, r1a.w));
    o.z = fmaxf(fmaxf(r0b.x, r0b.y), fmaxf(r1b.x, r1b.y));
    o.w = fmaxf(fmaxf(r0b.z, r0b.w), fmaxf(r1b.z, r1b.w));

    __stwt(&out4[tid], o);
}

extern "C" void kernel_launch(void* const* d_in, const int* in_sizes, int n_in,
                              void* d_out, int out_size) {
    const float4* in4 = (const float4*)d_in[0];
    float4* out4 = (float4*)d_out;

    const unsigned total = (unsigned)BC * OUT_H * OUT_ROW_F4;  // 16,777,216
    const int threads = 64;
    const unsigned blocks = total / threads;                   // 262,144

    maxpool2x2_kernel<<<blocks, threads>>>(in4, out4);
}